// round 11
// baseline (speedup 1.0000x reference)
#include <cuda_runtime.h>
#include <cuda_bf16.h>
#include <cstdint>

// CharEmb R9: warp-level mma.sync (bf16, split-precision) im2col GEMM
// + fused max-pool. tcgen05 is unavailable (harness PTX target is plain
// sm_103, no 'a' suffix) — mma.sync.m16n8k16.bf16 is baseline sm_80+ PTX
// and runs on the same tensor pipe via HMMA.
//
// Semantics: x_w[e,c] = table[ids[w][e>>1]][(e&1)*32 + c]  (raw .view)
// D[t,f] = sum_kk A[t,kk]*B[kk,f], kk=e*3+k, B[kk,f]=w[f*192+kk]
// out[w,f] = max_{t<30} D[t,f] + bias[f]
//
// Per word: M=32 (rows 30,31 padded+masked), N=128, K=192.
// Split bf16: v=hi+lo; D = Ah*Bh + Al*Bh + Ah*Bl (rel err ~1e-5).
// B fragments precomputed in mma register layout (hi+lo, 96 KB, L1-resident).
// A fragments built per k-step from fp32 smem (stride-33 padded gather).

#define NWORDS 16384
#define F_DIM  128
#define KSTEPS 12          // 192 / 16
#define SXS    33          // padded smem row stride (floats)

typedef unsigned long long u64;

// B fragments: [img(2)][ks(12)][ntile(16)][lane(32)] as u64 (2 regs packed)
#define BFRAG_U64_PER_IMG (KSTEPS * 16 * 32)   // 6144
__device__ __align__(16) u64 g_Bfrag[2 * BFRAG_U64_PER_IMG];

__device__ __forceinline__ void mma_bf16(float* d, const uint32_t* a,
                                         uint32_t b0, uint32_t b1) {
    asm volatile(
        "mma.sync.aligned.m16n8k16.row.col.f32.bf16.bf16.f32 "
        "{%0,%1,%2,%3}, {%4,%5,%6,%7}, {%8,%9}, {%0,%1,%2,%3};"
        : "+f"(d[0]), "+f"(d[1]), "+f"(d[2]), "+f"(d[3])
        : "r"(a[0]), "r"(a[1]), "r"(a[2]), "r"(a[3]), "r"(b0), "r"(b1));
}

// hi = bf16x2(va,vb) (low half = va); lo = bf16x2 of residuals
__device__ __forceinline__ void split2(float va, float vb,
                                       uint32_t& hi, uint32_t& lo) {
    __nv_bfloat162 h2 = __float22bfloat162_rn(make_float2(va, vb));
    float2 hf = __bfloat1622float2(h2);
    __nv_bfloat162 l2 = __float22bfloat162_rn(make_float2(va - hf.x, vb - hf.y));
    hi = *reinterpret_cast<uint32_t*>(&h2);
    lo = *reinterpret_cast<uint32_t*>(&l2);
}

// ---------- prep: B fragments in mma layout ----------
// For k-step ks, ntile nt: B frag reg r holds B[k,n] pairs at
// k = ks*16 + 2*tig + 8r (+1), n = nt*8 + gid. B[kk,f] = w[f*192 + kk].
__global__ __launch_bounds__(256) void prep_b_kernel(const float* __restrict__ w) {
    int idx = blockIdx.x * blockDim.x + threadIdx.x;
    if (idx >= KSTEPS * 16 * 32) return;
    int lane = idx & 31;
    int nt   = (idx >> 5) & 15;
    int ks   = idx >> 9;
    int tig = lane & 3, gid = lane >> 2;
    int f = nt * 8 + gid;

    uint32_t h[2], l[2];
    #pragma unroll
    for (int r = 0; r < 2; ++r) {
        int k0 = ks * 16 + 2 * tig + 8 * r;
        split2(w[f * 192 + k0], w[f * 192 + k0 + 1], h[r], l[r]);
    }
    u64 hv = ((u64)h[1] << 32) | h[0];
    u64 lv = ((u64)l[1] << 32) | l[0];
    int o = (ks * 16 + nt) * 32 + lane;
    g_Bfrag[o] = hv;
    g_Bfrag[BFRAG_U64_PER_IMG + o] = lv;
}

// ---------- main ----------
__global__ __launch_bounds__(128) void charemb_kernel(
    const int*   __restrict__ ids,     // [NWORDS, 32]
    const float* __restrict__ table,   // [101, 64]
    const float* __restrict__ bias,    // [128]
    float*       __restrict__ out)     // [NWORDS, 128]
{
    __shared__ float sxf[64 * SXS];    // x_w[e][c], padded
    __shared__ float red[F_DIM];

    const int n    = blockIdx.x;
    const int tid  = threadIdx.x;
    const int wid  = tid >> 5;
    const int lane = tid & 31;
    const int tig  = lane & 3;
    const int gid  = lane >> 2;

    // ---- gather x: sxf[e][c] = table[id[e>>1]][(e&1)*32 + c] ----
    const int* idn = ids + n * 32;
    #pragma unroll
    for (int j = 0; j < 16; ++j) {
        int p = tid + j * 128;
        int e = p >> 5, c = p & 31;
        sxf[e * SXS + c] = __ldg(table + __ldg(idn + (e >> 1)) * 64 + (e & 1) * 32 + c);
    }
    __syncthreads();

    // accumulators: d[mt][ntl][4]
    float d[2][4][4];
    #pragma unroll
    for (int mt = 0; mt < 2; ++mt)
        #pragma unroll
        for (int l = 0; l < 4; ++l)
            #pragma unroll
            for (int r = 0; r < 4; ++r) d[mt][l][r] = 0.0f;

    const u64* bfr = g_Bfrag;

    for (int ks = 0; ks < KSTEPS; ++ks) {
        // 4 kk columns for this lane
        int kk0 = ks * 16 + 2 * tig;
        int e0 = kk0 / 3,       dk0 = kk0 - 3 * e0;
        int e1 = (kk0 + 1) / 3, dk1 = (kk0 + 1) - 3 * e1;
        int e8 = (kk0 + 8) / 3, dk8 = (kk0 + 8) - 3 * e8;
        int e9 = (kk0 + 9) / 3, dk9 = (kk0 + 9) - 3 * e9;

        // B fragments (hi + lo), coalesced LDG.64, L1-resident
        u64 bh[4], bl[4];
        #pragma unroll
        for (int l = 0; l < 4; ++l) {
            int o = (ks * 16 + (wid * 4 + l)) * 32 + lane;
            bh[l] = __ldg(bfr + o);
            bl[l] = __ldg(bfr + BFRAG_U64_PER_IMG + o);
        }

        #pragma unroll
        for (int mt = 0; mt < 2; ++mt) {
            int t0 = mt * 16 + gid;
            int t1 = t0 + 8;
            // clamp c to 31 for padded rows (t=30,31), masked in epilogue
            int c00 = min(t0 + dk0, 31), c01 = min(t0 + dk1, 31);
            int c10 = min(t1 + dk0, 31), c11 = min(t1 + dk1, 31);
            int c08 = min(t0 + dk8, 31), c09 = min(t0 + dk9, 31);
            int c18 = min(t1 + dk8, 31), c19 = min(t1 + dk9, 31);

            uint32_t ah[4], al[4];
            split2(sxf[e0 * SXS + c00], sxf[e1 * SXS + c01], ah[0], al[0]);
            split2(sxf[e0 * SXS + c10], sxf[e1 * SXS + c11], ah[1], al[1]);
            split2(sxf[e8 * SXS + c08], sxf[e9 * SXS + c09], ah[2], al[2]);
            split2(sxf[e8 * SXS + c18], sxf[e9 * SXS + c19], ah[3], al[3]);

            #pragma unroll
            for (int l = 0; l < 4; ++l) {
                uint32_t b0 = (uint32_t)bh[l], b1 = (uint32_t)(bh[l] >> 32);
                uint32_t c0 = (uint32_t)bl[l], c1 = (uint32_t)(bl[l] >> 32);
                mma_bf16(d[mt][l], ah, b0, b1);   // Ah*Bh
                mma_bf16(d[mt][l], al, b0, b1);   // Al*Bh
                mma_bf16(d[mt][l], ah, c0, c1);   // Ah*Bl
            }
        }
    }

    // ---- epilogue: max over t<30 per filter column ----
    // c-frag rows: c0,c1 -> row mt*16+gid ; c2,c3 -> row mt*16+gid+8.
    // Invalid rows: mt=1, +8 half, gid>=6 (rows 30,31).
    #pragma unroll
    for (int l = 0; l < 4; ++l) {
        float ve = fmaxf(d[0][l][0], d[0][l][2]);
        float vo = fmaxf(d[0][l][1], d[0][l][3]);
        ve = fmaxf(ve, d[1][l][0]);
        vo = fmaxf(vo, d[1][l][1]);
        if (gid < 6) {
            ve = fmaxf(ve, d[1][l][2]);
            vo = fmaxf(vo, d[1][l][3]);
        }
        #pragma unroll
        for (int s = 4; s < 32; s <<= 1) {
            ve = fmaxf(ve, __shfl_xor_sync(0xffffffffu, ve, s));
            vo = fmaxf(vo, __shfl_xor_sync(0xffffffffu, vo, s));
        }
        if (gid == 0) {
            int f = (wid * 4 + l) * 8 + 2 * tig;
            red[f]     = ve;
            red[f + 1] = vo;
        }
    }
    __syncthreads();

    out[n * F_DIM + tid] = red[tid] + __ldg(bias + tid);
}

extern "C" void kernel_launch(void* const* d_in, const int* in_sizes, int n_in,
                              void* d_out, int out_size) {
    const int*   ids   = (const int*)  d_in[0];
    const float* table = (const float*)d_in[1];
    const float* w     = (const float*)d_in[2];
    const float* bias  = (const float*)d_in[3];
    float* out = (float*)d_out;

    prep_b_kernel<<<(KSTEPS * 16 * 32 + 255) / 256, 256>>>(w);
    charemb_kernel<<<NWORDS, 128>>>(ids, table, bias, out);
}

// round 12
// speedup vs baseline: 1.4118x; 1.4118x over previous
#include <cuda_runtime.h>
#include <cuda_bf16.h>
#include <cstdint>

// CharEmb R11: mma.sync bf16 split-precision im2col GEMM + fused max-pool,
// with block-shared A-fragment staging.
//
// R9 was ALU-bound (48.3%): every warp rebuilt identical A fragments (split2
// cvt + clamps + scattered LDS) per k-step. R11 builds each (ks, mt) fragment
// set ONCE per block (warp w builds ks = 3w..3w+2) into smem as 4 SoA u64
// arrays; the MMA mainloop is then pure LDG.128(B) + LDS.64(A) + HMMA.
//
// Math identical to R9: D = Ah*Bh + Al*Bh + Ah*Bl (split bf16, rel ~2e-6).
// out[w,f] = max_{t<30} D[t,f] + bias[f]; rows 30,31 padded + masked.

#define NWORDS 16384
#define F_DIM  128
#define KSTEPS 12
#define SXS    33

typedef unsigned long long u64;

// B fragments: [ks][nt][lane] -> ulonglong2{ hi: (b0,b1), lo: (b0,b1) }
__device__ __align__(16) ulonglong2 g_Bfrag[KSTEPS * 16 * 32];   // 96 KB

__device__ __forceinline__ void mma_bf16(float* d, const uint32_t* a,
                                         uint32_t b0, uint32_t b1) {
    asm volatile(
        "mma.sync.aligned.m16n8k16.row.col.f32.bf16.bf16.f32 "
        "{%0,%1,%2,%3}, {%4,%5,%6,%7}, {%8,%9}, {%0,%1,%2,%3};"
        : "+f"(d[0]), "+f"(d[1]), "+f"(d[2]), "+f"(d[3])
        : "r"(a[0]), "r"(a[1]), "r"(a[2]), "r"(a[3]), "r"(b0), "r"(b1));
}

__device__ __forceinline__ void split2(float va, float vb,
                                       uint32_t& hi, uint32_t& lo) {
    __nv_bfloat162 h2 = __float22bfloat162_rn(make_float2(va, vb));
    float2 hf = __bfloat1622float2(h2);
    __nv_bfloat162 l2 = __float22bfloat162_rn(make_float2(va - hf.x, vb - hf.y));
    hi = *reinterpret_cast<uint32_t*>(&h2);
    lo = *reinterpret_cast<uint32_t*>(&l2);
}

// ---------- prep: B fragments in mma layout, hi/lo interleaved ----------
__global__ __launch_bounds__(256) void prep_b_kernel(const float* __restrict__ w) {
    int idx = blockIdx.x * blockDim.x + threadIdx.x;
    if (idx >= KSTEPS * 16 * 32) return;
    int lane = idx & 31;
    int nt   = (idx >> 5) & 15;
    int ks   = idx >> 9;
    int tig = lane & 3, gid = lane >> 2;
    int f = nt * 8 + gid;

    uint32_t h[2], l[2];
    #pragma unroll
    for (int r = 0; r < 2; ++r) {
        int k0 = ks * 16 + 2 * tig + 8 * r;
        split2(w[f * 192 + k0], w[f * 192 + k0 + 1], h[r], l[r]);
    }
    ulonglong2 v;
    v.x = ((u64)h[1] << 32) | h[0];
    v.y = ((u64)l[1] << 32) | l[0];
    g_Bfrag[(ks * 16 + nt) * 32 + lane] = v;
}

// ---------- main ----------
__global__ __launch_bounds__(128) void charemb_kernel(
    const int*   __restrict__ ids,     // [NWORDS, 32]
    const float* __restrict__ table,   // [101, 64]
    const float* __restrict__ bias,    // [128]
    float*       __restrict__ out)     // [NWORDS, 128]
{
    __shared__ float sxf[64 * SXS];              // 8448 B
    __shared__ u64   sa[4][KSTEPS * 2 * 32];     // 24576 B: SoA A fragments
    __shared__ float red[F_DIM];

    const int n    = blockIdx.x;
    const int tid  = threadIdx.x;
    const int wid  = tid >> 5;
    const int lane = tid & 31;
    const int tig  = lane & 3;
    const int gid  = lane >> 2;

    // ---- gather x: sxf[e][c] = table[id[e>>1]][(e&1)*32 + c] ----
    const int* idn = ids + n * 32;
    #pragma unroll
    for (int j = 0; j < 16; ++j) {
        int p = tid + j * 128;
        int e = p >> 5, c = p & 31;
        sxf[e * SXS + c] = __ldg(table + __ldg(idn + (e >> 1)) * 64 + (e & 1) * 32 + c);
    }
    __syncthreads();

    // ---- build A fragments ONCE: warp w handles ks = 3w .. 3w+2 ----
    #pragma unroll
    for (int i = 0; i < 3; ++i) {
        int ks  = wid * 3 + i;
        int kk0 = ks * 16 + 2 * tig;
        int e0 = kk0 / 3,       dk0 = kk0 - 3 * e0;
        int e1 = (kk0 + 1) / 3, dk1 = (kk0 + 1) - 3 * e1;
        int e8 = (kk0 + 8) / 3, dk8 = (kk0 + 8) - 3 * e8;
        int e9 = (kk0 + 9) / 3, dk9 = (kk0 + 9) - 3 * e9;

        #pragma unroll
        for (int mt = 0; mt < 2; ++mt) {
            int t0 = mt * 16 + gid;
            int t1 = t0 + 8;
            int c00 = min(t0 + dk0, 31), c01 = min(t0 + dk1, 31);
            int c10 = min(t1 + dk0, 31), c11 = min(t1 + dk1, 31);
            int c08 = min(t0 + dk8, 31), c09 = min(t0 + dk9, 31);
            int c18 = min(t1 + dk8, 31), c19 = min(t1 + dk9, 31);

            uint32_t ah[4], al[4];
            split2(sxf[e0 * SXS + c00], sxf[e1 * SXS + c01], ah[0], al[0]);
            split2(sxf[e0 * SXS + c10], sxf[e1 * SXS + c11], ah[1], al[1]);
            split2(sxf[e8 * SXS + c08], sxf[e9 * SXS + c09], ah[2], al[2]);
            split2(sxf[e8 * SXS + c18], sxf[e9 * SXS + c19], ah[3], al[3]);

            int o = (ks * 2 + mt) * 32 + lane;
            sa[0][o] = ((u64)ah[1] << 32) | ah[0];
            sa[1][o] = ((u64)ah[3] << 32) | ah[2];
            sa[2][o] = ((u64)al[1] << 32) | al[0];
            sa[3][o] = ((u64)al[3] << 32) | al[2];
        }
    }
    __syncthreads();

    // ---- MMA mainloop: pure LDG.128 + LDS.64 + HMMA ----
    float d[2][4][4];
    #pragma unroll
    for (int mt = 0; mt < 2; ++mt)
        #pragma unroll
        for (int l = 0; l < 4; ++l)
            #pragma unroll
            for (int r = 0; r < 4; ++r) d[mt][l][r] = 0.0f;

    #pragma unroll 4
    for (int ks = 0; ks < KSTEPS; ++ks) {
        ulonglong2 b[4];
        #pragma unroll
        for (int l = 0; l < 4; ++l)
            b[l] = g_Bfrag[(ks * 16 + wid * 4 + l) * 32 + lane];

        #pragma unroll
        for (int mt = 0; mt < 2; ++mt) {
            int o = (ks * 2 + mt) * 32 + lane;
            u64 a0 = sa[0][o], a1 = sa[1][o], a2 = sa[2][o], a3 = sa[3][o];
            uint32_t ah[4] = { (uint32_t)a0, (uint32_t)(a0 >> 32),
                               (uint32_t)a1, (uint32_t)(a1 >> 32) };
            uint32_t al[4] = { (uint32_t)a2, (uint32_t)(a2 >> 32),
                               (uint32_t)a3, (uint32_t)(a3 >> 32) };
            #pragma unroll
            for (int l = 0; l < 4; ++l) {
                uint32_t bh0 = (uint32_t)b[l].x, bh1 = (uint32_t)(b[l].x >> 32);
                uint32_t bl0 = (uint32_t)b[l].y, bl1 = (uint32_t)(b[l].y >> 32);
                mma_bf16(d[mt][l], ah, bh0, bh1);   // Ah*Bh
                mma_bf16(d[mt][l], al, bh0, bh1);   // Al*Bh
                mma_bf16(d[mt][l], ah, bl0, bl1);   // Ah*Bl
            }
        }
    }

    // ---- epilogue: max over t<30 per filter column ----
    #pragma unroll
    for (int l = 0; l < 4; ++l) {
        float ve = fmaxf(d[0][l][0], d[0][l][2]);
        float vo = fmaxf(d[0][l][1], d[0][l][3]);
        ve = fmaxf(ve, d[1][l][0]);
        vo = fmaxf(vo, d[1][l][1]);
        if (gid < 6) {
            ve = fmaxf(ve, d[1][l][2]);
            vo = fmaxf(vo, d[1][l][3]);
        }
        #pragma unroll
        for (int s = 4; s < 32; s <<= 1) {
            ve = fmaxf(ve, __shfl_xor_sync(0xffffffffu, ve, s));
            vo = fmaxf(vo, __shfl_xor_sync(0xffffffffu, vo, s));
        }
        if (gid == 0) {
            int f = (wid * 4 + l) * 8 + 2 * tig;
            red[f]     = ve;
            red[f + 1] = vo;
        }
    }
    __syncthreads();

    out[n * F_DIM + tid] = red[tid] + __ldg(bias + tid);
}

extern "C" void kernel_launch(void* const* d_in, const int* in_sizes, int n_in,
                              void* d_out, int out_size) {
    const int*   ids   = (const int*)  d_in[0];
    const float* table = (const float*)d_in[1];
    const float* w     = (const float*)d_in[2];
    const float* bias  = (const float*)d_in[3];
    float* out = (float*)d_out;

    prep_b_kernel<<<(KSTEPS * 16 * 32 + 255) / 256, 256>>>(w);
    charemb_kernel<<<NWORDS, 128>>>(ids, table, bias, out);
}

// round 13
// speedup vs baseline: 1.8737x; 1.3272x over previous
#include <cuda_runtime.h>
#include <cuda_fp16.h>
#include <cstdint>

// CharEmb R12: mma.sync fp16 split-precision (2-term) im2col GEMM + max-pool.
//
// R11 (bf16 3-term) hit its tensor floor (~126us at tensor=61%). fp16's 11-bit
// mantissa lets us drop to TWO mma terms: D = Ah*Bh + Al*Bh, with B quantized
// to fp16 hi only. Residual error = B quantization only: ~2-3e-4 rel (vs 1e-3
// threshold). MMA count x2/3, B fragment traffic x1/2 (u64 instead of u128).
//
// Semantics: x_w[e,c] = table[ids[w][e>>1]][(e&1)*32 + c]  (raw .view)
// out[w,f] = max_{t<30} sum_kk A[t,kk] B[kk,f] + bias[f];  kk = e*3+k.
// M=32 per word (rows 30,31 padded+masked), N=128, K=192.

#define NWORDS 16384
#define F_DIM  128
#define KSTEPS 12
#define SXS    33

typedef unsigned long long u64;

// B fragments (hi only): [ks][nt][lane] -> u64 = (b0, b1)
__device__ __align__(16) u64 g_Bfrag[KSTEPS * 16 * 32];   // 48 KB

__device__ __forceinline__ void mma_f16(float* d, const uint32_t* a,
                                        uint32_t b0, uint32_t b1) {
    asm volatile(
        "mma.sync.aligned.m16n8k16.row.col.f32.f16.f16.f32 "
        "{%0,%1,%2,%3}, {%4,%5,%6,%7}, {%8,%9}, {%0,%1,%2,%3};"
        : "+f"(d[0]), "+f"(d[1]), "+f"(d[2]), "+f"(d[3])
        : "r"(a[0]), "r"(a[1]), "r"(a[2]), "r"(a[3]), "r"(b0), "r"(b1));
}

// fp16 split: hi = h2(va,vb), lo = h2 of residuals
__device__ __forceinline__ void split2h(float va, float vb,
                                        uint32_t& hi, uint32_t& lo) {
    __half2 h2 = __float22half2_rn(make_float2(va, vb));
    float2 hf = __half22float2(h2);
    __half2 l2 = __float22half2_rn(make_float2(va - hf.x, vb - hf.y));
    hi = *reinterpret_cast<uint32_t*>(&h2);
    lo = *reinterpret_cast<uint32_t*>(&l2);
}

// ---------- prep: B hi fragments in mma layout ----------
__global__ __launch_bounds__(256) void prep_b_kernel(const float* __restrict__ w) {
    int idx = blockIdx.x * blockDim.x + threadIdx.x;
    if (idx >= KSTEPS * 16 * 32) return;
    int lane = idx & 31;
    int nt   = (idx >> 5) & 15;
    int ks   = idx >> 9;
    int tig = lane & 3, gid = lane >> 2;
    int f = nt * 8 + gid;

    uint32_t h[2];
    #pragma unroll
    for (int r = 0; r < 2; ++r) {
        int k0 = ks * 16 + 2 * tig + 8 * r;
        __half2 h2 = __float22half2_rn(make_float2(w[f * 192 + k0],
                                                   w[f * 192 + k0 + 1]));
        h[r] = *reinterpret_cast<uint32_t*>(&h2);
    }
    g_Bfrag[(ks * 16 + nt) * 32 + lane] = ((u64)h[1] << 32) | h[0];
}

// ---------- main ----------
__global__ __launch_bounds__(128) void charemb_kernel(
    const int*   __restrict__ ids,     // [NWORDS, 32]
    const float* __restrict__ table,   // [101, 64]
    const float* __restrict__ bias,    // [128]
    float*       __restrict__ out)     // [NWORDS, 128]
{
    __shared__ float sxf[64 * SXS];              // 8448 B
    __shared__ u64   sa[4][KSTEPS * 2 * 32];     // 24576 B: ah0,ah1,al0,al1 SoA
    __shared__ float red[F_DIM];

    const int n    = blockIdx.x;
    const int tid  = threadIdx.x;
    const int wid  = tid >> 5;
    const int lane = tid & 31;
    const int tig  = lane & 3;
    const int gid  = lane >> 2;

    // ---- gather x ----
    const int* idn = ids + n * 32;
    #pragma unroll
    for (int j = 0; j < 16; ++j) {
        int p = tid + j * 128;
        int e = p >> 5, c = p & 31;
        sxf[e * SXS + c] = __ldg(table + __ldg(idn + (e >> 1)) * 64 + (e & 1) * 32 + c);
    }
    __syncthreads();

    // ---- build A fragments once: warp w -> ks = 3w..3w+2 ----
    #pragma unroll
    for (int i = 0; i < 3; ++i) {
        int ks  = wid * 3 + i;
        int kk0 = ks * 16 + 2 * tig;
        int e0 = kk0 / 3,       dk0 = kk0 - 3 * e0;
        int e1 = (kk0 + 1) / 3, dk1 = (kk0 + 1) - 3 * e1;
        int e8 = (kk0 + 8) / 3, dk8 = (kk0 + 8) - 3 * e8;
        int e9 = (kk0 + 9) / 3, dk9 = (kk0 + 9) - 3 * e9;

        #pragma unroll
        for (int mt = 0; mt < 2; ++mt) {
            int t0 = mt * 16 + gid;
            int t1 = t0 + 8;
            int c00 = min(t0 + dk0, 31), c01 = min(t0 + dk1, 31);
            int c10 = min(t1 + dk0, 31), c11 = min(t1 + dk1, 31);
            int c08 = min(t0 + dk8, 31), c09 = min(t0 + dk9, 31);
            int c18 = min(t1 + dk8, 31), c19 = min(t1 + dk9, 31);

            uint32_t ah[4], al[4];
            split2h(sxf[e0 * SXS + c00], sxf[e1 * SXS + c01], ah[0], al[0]);
            split2h(sxf[e0 * SXS + c10], sxf[e1 * SXS + c11], ah[1], al[1]);
            split2h(sxf[e8 * SXS + c08], sxf[e9 * SXS + c09], ah[2], al[2]);
            split2h(sxf[e8 * SXS + c18], sxf[e9 * SXS + c19], ah[3], al[3]);

            int o = (ks * 2 + mt) * 32 + lane;
            sa[0][o] = ((u64)ah[1] << 32) | ah[0];
            sa[1][o] = ((u64)ah[3] << 32) | ah[2];
            sa[2][o] = ((u64)al[1] << 32) | al[0];
            sa[3][o] = ((u64)al[3] << 32) | al[2];
        }
    }
    __syncthreads();

    // ---- MMA mainloop: LDG.64(Bh) + LDS.64(A) + HMMA, 2 terms ----
    float d[2][4][4];
    #pragma unroll
    for (int mt = 0; mt < 2; ++mt)
        #pragma unroll
        for (int l = 0; l < 4; ++l)
            #pragma unroll
            for (int r = 0; r < 4; ++r) d[mt][l][r] = 0.0f;

    #pragma unroll 4
    for (int ks = 0; ks < KSTEPS; ++ks) {
        u64 b[4];
        #pragma unroll
        for (int l = 0; l < 4; ++l)
            b[l] = __ldg(g_Bfrag + (ks * 16 + wid * 4 + l) * 32 + lane);

        #pragma unroll
        for (int mt = 0; mt < 2; ++mt) {
            int o = (ks * 2 + mt) * 32 + lane;
            u64 a0 = sa[0][o], a1 = sa[1][o], a2 = sa[2][o], a3 = sa[3][o];
            uint32_t ah[4] = { (uint32_t)a0, (uint32_t)(a0 >> 32),
                               (uint32_t)a1, (uint32_t)(a1 >> 32) };
            uint32_t al[4] = { (uint32_t)a2, (uint32_t)(a2 >> 32),
                               (uint32_t)a3, (uint32_t)(a3 >> 32) };
            #pragma unroll
            for (int l = 0; l < 4; ++l) {
                uint32_t b0 = (uint32_t)b[l], b1 = (uint32_t)(b[l] >> 32);
                mma_f16(d[mt][l], ah, b0, b1);   // Ah*Bh
                mma_f16(d[mt][l], al, b0, b1);   // Al*Bh
            }
        }
    }

    // ---- epilogue: max over t<30 ----
    #pragma unroll
    for (int l = 0; l < 4; ++l) {
        float ve = fmaxf(d[0][l][0], d[0][l][2]);
        float vo = fmaxf(d[0][l][1], d[0][l][3]);
        ve = fmaxf(ve, d[1][l][0]);
        vo = fmaxf(vo, d[1][l][1]);
        if (gid < 6) {
            ve = fmaxf(ve, d[1][l][2]);
            vo = fmaxf(vo, d[1][l][3]);
        }
        #pragma unroll
        for (int s = 4; s < 32; s <<= 1) {
            ve = fmaxf(ve, __shfl_xor_sync(0xffffffffu, ve, s));
            vo = fmaxf(vo, __shfl_xor_sync(0xffffffffu, vo, s));
        }
        if (gid == 0) {
            int f = (wid * 4 + l) * 8 + 2 * tig;
            red[f]     = ve;
            red[f + 1] = vo;
        }
    }
    __syncthreads();

    out[n * F_DIM + tid] = red[tid] + __ldg(bias + tid);
}

extern "C" void kernel_launch(void* const* d_in, const int* in_sizes, int n_in,
                              void* d_out, int out_size) {
    const int*   ids   = (const int*)  d_in[0];
    const float* table = (const float*)d_in[1];
    const float* w     = (const float*)d_in[2];
    const float* bias  = (const float*)d_in[3];
    float* out = (float*)d_out;

    prep_b_kernel<<<(KSTEPS * 16 * 32 + 255) / 256, 256>>>(w);
    charemb_kernel<<<NWORDS, 128>>>(ids, table, bias, out);
}

// round 14
// speedup vs baseline: 2.6416x; 1.4098x over previous
#include <cuda_runtime.h>
#include <cuda_fp16.h>
#include <cstdint>

// CharEmb R13: pure-fp16 mma.sync im2col GEMM + fused max-pool (1 term).
//
// Precision calibration from R12: B-quantized-to-fp16 alone measured
// rel_err = 1.02e-4. Quantizing A too adds the same error in quadrature
// -> ~1.5e-4, still ~7x under the 1e-3 threshold. So drop the Al*Bh term:
// D = Ah*Bh only. HMMA count halves (384/block), A smem traffic halves.
//
// Semantics: x_w[e,c] = table[ids[w][e>>1]][(e&1)*32 + c]  (raw .view)
// out[w,f] = max_{t<30} sum_kk A[t,kk] B[kk,f] + bias[f];  kk = e*3+k.
// M=32 per word (rows 30,31 padded via c-clamp + masked), N=128, K=192.

#define NWORDS 16384
#define F_DIM  128
#define KSTEPS 12
#define SXS    33

typedef unsigned long long u64;

// B fragments (fp16): [ks][nt][lane] -> u64 = (b0, b1)
__device__ __align__(16) u64 g_Bfrag[KSTEPS * 16 * 32];   // 48 KB

__device__ __forceinline__ void mma_f16(float* d, const uint32_t* a,
                                        uint32_t b0, uint32_t b1) {
    asm volatile(
        "mma.sync.aligned.m16n8k16.row.col.f32.f16.f16.f32 "
        "{%0,%1,%2,%3}, {%4,%5,%6,%7}, {%8,%9}, {%0,%1,%2,%3};"
        : "+f"(d[0]), "+f"(d[1]), "+f"(d[2]), "+f"(d[3])
        : "r"(a[0]), "r"(a[1]), "r"(a[2]), "r"(a[3]), "r"(b0), "r"(b1));
}

__device__ __forceinline__ uint32_t pack_h2(float va, float vb) {
    __half2 h2 = __float22half2_rn(make_float2(va, vb));
    return *reinterpret_cast<uint32_t*>(&h2);
}

// ---------- prep: B fp16 fragments in mma layout ----------
__global__ __launch_bounds__(256) void prep_b_kernel(const float* __restrict__ w) {
    int idx = blockIdx.x * blockDim.x + threadIdx.x;
    if (idx >= KSTEPS * 16 * 32) return;
    int lane = idx & 31;
    int nt   = (idx >> 5) & 15;
    int ks   = idx >> 9;
    int tig = lane & 3, gid = lane >> 2;
    int f = nt * 8 + gid;

    uint32_t h[2];
    #pragma unroll
    for (int r = 0; r < 2; ++r) {
        int k0 = ks * 16 + 2 * tig + 8 * r;
        h[r] = pack_h2(w[f * 192 + k0], w[f * 192 + k0 + 1]);
    }
    g_Bfrag[(ks * 16 + nt) * 32 + lane] = ((u64)h[1] << 32) | h[0];
}

// ---------- main ----------
__global__ __launch_bounds__(128) void charemb_kernel(
    const int*   __restrict__ ids,     // [NWORDS, 32]
    const float* __restrict__ table,   // [101, 64]
    const float* __restrict__ bias,    // [128]
    float*       __restrict__ out)     // [NWORDS, 128]
{
    __shared__ float      sxf[64 * SXS];             // 8448 B
    __shared__ ulonglong2 sa[KSTEPS * 2 * 32];       // 12288 B: A fp16 fragments
    __shared__ float      red[F_DIM];

    const int n    = blockIdx.x;
    const int tid  = threadIdx.x;
    const int wid  = tid >> 5;
    const int lane = tid & 31;
    const int tig  = lane & 3;
    const int gid  = lane >> 2;

    // ---- gather x: sxf[e][c] = table[id[e>>1]][(e&1)*32 + c] ----
    const int* idn = ids + n * 32;
    #pragma unroll
    for (int j = 0; j < 16; ++j) {
        int p = tid + j * 128;
        int e = p >> 5, c = p & 31;
        sxf[e * SXS + c] = __ldg(table + __ldg(idn + (e >> 1)) * 64 + (e & 1) * 32 + c);
    }
    __syncthreads();

    // ---- build fp16 A fragments once: warp w -> ks = 3w..3w+2 ----
    #pragma unroll
    for (int i = 0; i < 3; ++i) {
        int ks  = wid * 3 + i;
        int kk0 = ks * 16 + 2 * tig;
        int e0 = kk0 / 3,       dk0 = kk0 - 3 * e0;
        int e1 = (kk0 + 1) / 3, dk1 = (kk0 + 1) - 3 * e1;
        int e8 = (kk0 + 8) / 3, dk8 = (kk0 + 8) - 3 * e8;
        int e9 = (kk0 + 9) / 3, dk9 = (kk0 + 9) - 3 * e9;

        #pragma unroll
        for (int mt = 0; mt < 2; ++mt) {
            int t0 = mt * 16 + gid;
            int t1 = t0 + 8;
            int c00 = min(t0 + dk0, 31), c01 = min(t0 + dk1, 31);
            int c10 = min(t1 + dk0, 31), c11 = min(t1 + dk1, 31);
            int c08 = min(t0 + dk8, 31), c09 = min(t0 + dk9, 31);
            int c18 = min(t1 + dk8, 31), c19 = min(t1 + dk9, 31);

            uint32_t a0 = pack_h2(sxf[e0 * SXS + c00], sxf[e1 * SXS + c01]);
            uint32_t a1 = pack_h2(sxf[e0 * SXS + c10], sxf[e1 * SXS + c11]);
            uint32_t a2 = pack_h2(sxf[e8 * SXS + c08], sxf[e9 * SXS + c09]);
            uint32_t a3 = pack_h2(sxf[e8 * SXS + c18], sxf[e9 * SXS + c19]);

            ulonglong2 v;
            v.x = ((u64)a1 << 32) | a0;
            v.y = ((u64)a3 << 32) | a2;
            sa[(ks * 2 + mt) * 32 + lane] = v;
        }
    }
    __syncthreads();

    // ---- MMA mainloop: LDG.64(B) + LDS.128(A) + HMMA ----
    float d[2][4][4];
    #pragma unroll
    for (int mt = 0; mt < 2; ++mt)
        #pragma unroll
        for (int l = 0; l < 4; ++l)
            #pragma unroll
            for (int r = 0; r < 4; ++r) d[mt][l][r] = 0.0f;

    #pragma unroll 4
    for (int ks = 0; ks < KSTEPS; ++ks) {
        u64 b[4];
        #pragma unroll
        for (int l = 0; l < 4; ++l)
            b[l] = __ldg(g_Bfrag + (ks * 16 + wid * 4 + l) * 32 + lane);

        #pragma unroll
        for (int mt = 0; mt < 2; ++mt) {
            ulonglong2 av = sa[(ks * 2 + mt) * 32 + lane];
            uint32_t a[4] = { (uint32_t)av.x, (uint32_t)(av.x >> 32),
                              (uint32_t)av.y, (uint32_t)(av.y >> 32) };
            #pragma unroll
            for (int l = 0; l < 4; ++l)
                mma_f16(d[mt][l], a, (uint32_t)b[l], (uint32_t)(b[l] >> 32));
        }
    }

    // ---- epilogue: max over t<30 ----
    #pragma unroll
    for (int l = 0; l < 4; ++l) {
        float ve = fmaxf(d[0][l][0], d[0][l][2]);
        float vo = fmaxf(d[0][l][1], d[0][l][3]);
        ve = fmaxf(ve, d[1][l][0]);
        vo = fmaxf(vo, d[1][l][1]);
        if (gid < 6) {
            ve = fmaxf(ve, d[1][l][2]);
            vo = fmaxf(vo, d[1][l][3]);
        }
        #pragma unroll
        for (int s = 4; s < 32; s <<= 1) {
            ve = fmaxf(ve, __shfl_xor_sync(0xffffffffu, ve, s));
            vo = fmaxf(vo, __shfl_xor_sync(0xffffffffu, vo, s));
        }
        if (gid == 0) {
            int f = (wid * 4 + l) * 8 + 2 * tig;
            red[f]     = ve;
            red[f + 1] = vo;
        }
    }
    __syncthreads();

    out[n * F_DIM + tid] = red[tid] + __ldg(bias + tid);
}

extern "C" void kernel_launch(void* const* d_in, const int* in_sizes, int n_in,
                              void* d_out, int out_size) {
    const int*   ids   = (const int*)  d_in[0];
    const float* table = (const float*)d_in[1];
    const float* w     = (const float*)d_in[2];
    const float* bias  = (const float*)d_in[3];
    float* out = (float*)d_out;

    prep_b_kernel<<<(KSTEPS * 16 * 32 + 255) / 256, 256>>>(w);
    charemb_kernel<<<NWORDS, 128>>>(ids, table, bias, out);
}